// round 1
// baseline (speedup 1.0000x reference)
#include <cuda_runtime.h>
#include <math.h>

#define NMAX 100000
#define EMAX 1600000
#define DIN 256
#define DH 128
#define DOUT 10

// ---------------- scratch (no allocation allowed) ----------------
__device__ float g_h1[(size_t)NMAX * DH];     // x @ W1
__device__ float g_a1[(size_t)NMAX * DH];     // relu(agg(h1) + b1)
__device__ float g_h2[(size_t)NMAX * DOUT];   // a1 @ W2
__device__ int   g_deg[NMAX];
__device__ float g_dinv[NMAX];
__device__ int   g_rowptr[NMAX + 1];
__device__ int   g_cursor[NMAX];
__device__ int   g_csrsrc[EMAX];
__device__ int   g_is64;

// ---------------- edge dtype detection (int64 vs int32) ----------------
__global__ void detect_kernel(const void* ei, int E) {
    // If the buffer is genuine int64, every value is in [0, N) < 2^31.
    // If it is int32 data misread as int64, the high word is a random node id,
    // so values are >= 2^32 with overwhelming probability.
    const long long* p = (const long long*)ei;
    int m = E < 64 ? E : 64;
    int ok = 1;
    for (int i = 0; i < m; i++) {
        long long v = p[i];
        if (v < 0 || v >= (1LL << 31)) ok = 0;
    }
    g_is64 = ok;
}

__device__ __forceinline__ void get_edge(const void* ei, int e, int E, int& s, int& d) {
    if (g_is64) {
        const long long* p = (const long long*)ei;
        s = (int)p[e];
        d = (int)p[(size_t)E + e];
    } else {
        const int* p = (const int*)ei;
        s = p[e];
        d = p[E + e];
    }
}

// ---------------- CSR build ----------------
__global__ void init_kernel(int n) {
    int v = blockIdx.x * blockDim.x + threadIdx.x;
    if (v < n) g_deg[v] = 0;
}

__global__ void count_kernel(const void* ei, int E) {
    int stride = gridDim.x * blockDim.x;
    for (int e = blockIdx.x * blockDim.x + threadIdx.x; e < E; e += stride) {
        int s, d;
        get_edge(ei, e, E, s, d);
        atomicAdd(&g_deg[d], 1);
    }
}

// single-block exclusive scan of g_deg -> g_rowptr  (n up to 100352 with 1024 thr)
__global__ void scan_kernel(int n) {
    __shared__ int sums[1024];
    int tid = threadIdx.x;
    int chunk = (n + 1023) / 1024;
    int start = tid * chunk;
    int local = 0;
    for (int i = 0; i < chunk; i++) {
        int idx = start + i;
        if (idx < n) local += g_deg[idx];
    }
    sums[tid] = local;
    __syncthreads();
    // Hillis-Steele inclusive scan
    for (int off = 1; off < 1024; off <<= 1) {
        int add = (tid >= off) ? sums[tid - off] : 0;
        __syncthreads();
        sums[tid] += add;
        __syncthreads();
    }
    int run = sums[tid] - local;   // exclusive prefix of this thread's chunk
    for (int i = 0; i < chunk; i++) {
        int idx = start + i;
        if (idx < n) {
            g_rowptr[idx] = run;
            run += g_deg[idx];
        }
    }
    if (tid == 1023) g_rowptr[n] = sums[1023];
}

__global__ void prep_kernel(int n) {
    int v = blockIdx.x * blockDim.x + threadIdx.x;
    if (v < n) {
        g_dinv[v] = rsqrtf((float)(g_deg[v] + 1));  // +1 self loop
        g_cursor[v] = g_rowptr[v];
    }
}

__global__ void fill_kernel(const void* ei, int E) {
    int stride = gridDim.x * blockDim.x;
    for (int e = blockIdx.x * blockDim.x + threadIdx.x; e < E; e += stride) {
        int s, d;
        get_edge(ei, e, E, s, d);
        int pos = atomicAdd(&g_cursor[d], 1);
        g_csrsrc[pos] = s;
    }
}

// ---------------- GEMM1: h1 = x @ W1  (N x 256 @ 256 x 128) ----------------
// 128x128 block tile, BK=8, 8x8 per-thread register tile, 256 threads.
__global__ __launch_bounds__(256) void gemm1_kernel(const float* __restrict__ x,
                                                    const float* __restrict__ W, int n) {
    __shared__ float As[8][128];
    __shared__ float Bs[8][128];
    int tid = threadIdx.x;
    int blockRow = blockIdx.x * 128;

    int aRow = tid >> 1;            // 0..127
    int aCol = (tid & 1) * 4;       // 0 or 4
    int bR = tid >> 5;              // 0..7
    int bC = (tid & 31) * 4;        // 0..124

    int tRow = (tid >> 4) * 8;      // 0..120
    int tCol = (tid & 15) * 8;      // 0..120

    float acc[8][8];
#pragma unroll
    for (int i = 0; i < 8; i++)
#pragma unroll
        for (int j = 0; j < 8; j++) acc[i][j] = 0.f;

    int gr = blockRow + aRow;
    for (int k0 = 0; k0 < DIN; k0 += 8) {
        float4 av = (gr < n) ? *(const float4*)(x + (size_t)gr * DIN + k0 + aCol)
                             : make_float4(0.f, 0.f, 0.f, 0.f);
        As[aCol + 0][aRow] = av.x;
        As[aCol + 1][aRow] = av.y;
        As[aCol + 2][aRow] = av.z;
        As[aCol + 3][aRow] = av.w;
        *(float4*)(&Bs[bR][bC]) = *(const float4*)(W + (size_t)(k0 + bR) * DH + bC);
        __syncthreads();
#pragma unroll
        for (int k = 0; k < 8; k++) {
            float rm[8], rn[8];
            *(float4*)(&rm[0]) = *(const float4*)(&As[k][tRow]);
            *(float4*)(&rm[4]) = *(const float4*)(&As[k][tRow + 4]);
            *(float4*)(&rn[0]) = *(const float4*)(&Bs[k][tCol]);
            *(float4*)(&rn[4]) = *(const float4*)(&Bs[k][tCol + 4]);
#pragma unroll
            for (int i = 0; i < 8; i++)
#pragma unroll
                for (int j = 0; j < 8; j++) acc[i][j] = fmaf(rm[i], rn[j], acc[i][j]);
        }
        __syncthreads();
    }

#pragma unroll
    for (int i = 0; i < 8; i++) {
        int r = blockRow + tRow + i;
        if (r < n) {
            float* o = g_h1 + (size_t)r * DH + tCol;
            *(float4*)(o + 0) = make_float4(acc[i][0], acc[i][1], acc[i][2], acc[i][3]);
            *(float4*)(o + 4) = make_float4(acc[i][4], acc[i][5], acc[i][6], acc[i][7]);
        }
    }
}

// ---------------- Aggregation 1 (warp per node, gather via CSR) ----------------
__global__ __launch_bounds__(256) void agg1_kernel(const float* __restrict__ b1, int n) {
    int warp = (blockIdx.x * 256 + threadIdx.x) >> 5;
    int lane = threadIdx.x & 31;
    if (warp >= n) return;
    int v = warp;
    float dv = g_dinv[v];

    float4 acc = ((const float4*)(g_h1 + (size_t)v * DH))[lane];  // self loop
    float sw = dv * dv;
    acc.x *= sw; acc.y *= sw; acc.z *= sw; acc.w *= sw;

    int beg = g_rowptr[v], end = g_rowptr[v + 1];
    for (int base = beg; base < end; base += 32) {
        int j = base + lane;
        int s = 0;
        float w = 0.f;
        if (j < end) {
            s = g_csrsrc[j];
            w = g_dinv[s] * dv;
        }
        int cnt = min(32, end - base);
        for (int t = 0; t < cnt; t++) {
            int ss = __shfl_sync(0xffffffffu, s, t);
            float ww = __shfl_sync(0xffffffffu, w, t);
            float4 hv = ((const float4*)(g_h1 + (size_t)ss * DH))[lane];
            acc.x = fmaf(hv.x, ww, acc.x);
            acc.y = fmaf(hv.y, ww, acc.y);
            acc.z = fmaf(hv.z, ww, acc.z);
            acc.w = fmaf(hv.w, ww, acc.w);
        }
    }
    float4 b = ((const float4*)b1)[lane];
    acc.x = fmaxf(acc.x + b.x, 0.f);
    acc.y = fmaxf(acc.y + b.y, 0.f);
    acc.z = fmaxf(acc.z + b.z, 0.f);
    acc.w = fmaxf(acc.w + b.w, 0.f);
    ((float4*)(g_a1 + (size_t)v * DH))[lane] = acc;
}

// ---------------- GEMM2: h2 = a1 @ W2  (warp per row) ----------------
__global__ __launch_bounds__(256) void gemm2_kernel(const float* __restrict__ W2, int n) {
    __shared__ float Ws[DH * DOUT];
    for (int i = threadIdx.x; i < DH * DOUT; i += 256) Ws[i] = W2[i];
    __syncthreads();
    int warp = (blockIdx.x * 256 + threadIdx.x) >> 5;
    int lane = threadIdx.x & 31;
    if (warp >= n) return;

    float4 a = ((const float4*)(g_a1 + (size_t)warp * DH))[lane];
    float p[DOUT];
#pragma unroll
    for (int d = 0; d < DOUT; d++) p[d] = 0.f;
    int k0 = lane * 4;
    float av[4] = {a.x, a.y, a.z, a.w};
#pragma unroll
    for (int c = 0; c < 4; c++)
#pragma unroll
        for (int d = 0; d < DOUT; d++) p[d] = fmaf(av[c], Ws[(k0 + c) * DOUT + d], p[d]);
#pragma unroll
    for (int d = 0; d < DOUT; d++)
#pragma unroll
        for (int off = 16; off > 0; off >>= 1) p[d] += __shfl_down_sync(0xffffffffu, p[d], off);
    if (lane == 0) {
#pragma unroll
        for (int d = 0; d < DOUT; d++) g_h2[(size_t)warp * DOUT + d] = p[d];
    }
}

// ---------------- Aggregation 2 + bias + log_softmax + output ----------------
__global__ void agg2_kernel(const float* __restrict__ b2, float* out_h, float* out_lsm, int n) {
    int v = blockIdx.x * blockDim.x + threadIdx.x;
    if (v >= n) return;
    float dv = g_dinv[v];
    float acc[DOUT];
    const float* hv = g_h2 + (size_t)v * DOUT;
    float sw = dv * dv;
#pragma unroll
    for (int d = 0; d < DOUT; d++) acc[d] = hv[d] * sw;

    int beg = g_rowptr[v], end = g_rowptr[v + 1];
    for (int j = beg; j < end; j++) {
        int s = g_csrsrc[j];
        float w = g_dinv[s] * dv;
        const float* hs = g_h2 + (size_t)s * DOUT;
#pragma unroll
        for (int d = 0; d < DOUT; d++) acc[d] = fmaf(hs[d], w, acc[d]);
    }
#pragma unroll
    for (int d = 0; d < DOUT; d++) acc[d] += b2[d];

    float m = acc[0];
#pragma unroll
    for (int d = 1; d < DOUT; d++) m = fmaxf(m, acc[d]);
    float se = 0.f;
#pragma unroll
    for (int d = 0; d < DOUT; d++) se += expf(acc[d] - m);
    float lse = m + logf(se);

    float* oh = out_h + (size_t)v * DOUT;
    float* ol = out_lsm + (size_t)v * DOUT;
#pragma unroll
    for (int d = 0; d < DOUT; d++) oh[d] = acc[d];
#pragma unroll
    for (int d = 0; d < DOUT; d++) ol[d] = acc[d] - lse;
}

// ---------------- launch ----------------
extern "C" void kernel_launch(void* const* d_in, const int* in_sizes, int n_in,
                              void* d_out, int out_size) {
    const float* x  = (const float*)d_in[0];
    const void*  ei = d_in[1];
    const float* W1 = (const float*)d_in[2];
    const float* b1 = (const float*)d_in[3];
    const float* W2 = (const float*)d_in[4];
    const float* b2 = (const float*)d_in[5];

    int n = in_sizes[0] / DIN;
    int E = in_sizes[1] / 2;
    if (n > NMAX) n = NMAX;
    if (E > EMAX) E = EMAX;

    float* out = (float*)d_out;
    float* out_h;
    float* out_lsm;
    if (out_size >= 2 * n * DOUT) {
        out_h = out;
        out_lsm = out + (size_t)n * DOUT;
    } else {
        out_h = out;       // overlapping: log_softmax (written last) wins
        out_lsm = out;
    }

    int nb256 = (n + 255) / 256;
    int eb = 2048;

    detect_kernel<<<1, 1>>>(ei, E);
    init_kernel<<<nb256, 256>>>(n);
    count_kernel<<<eb, 256>>>(ei, E);
    scan_kernel<<<1, 1024>>>(n);
    prep_kernel<<<nb256, 256>>>(n);
    fill_kernel<<<eb, 256>>>(ei, E);

    gemm1_kernel<<<(n + 127) / 128, 256>>>(x, W1, n);
    agg1_kernel<<<(n * 32 + 255) / 256, 256>>>(b1, n);
    gemm2_kernel<<<(n * 32 + 255) / 256, 256>>>(W2, n);
    agg2_kernel<<<nb256, 256>>>(b2, out_h, out_lsm, n);
}

// round 4
// speedup vs baseline: 1.2768x; 1.2768x over previous
#include <cuda_runtime.h>
#include <math.h>

#define NMAX 100000
#define EMAX 1600000
#define DIN 256
#define DH 128
#define DOUT 10
#define SCAN_B 1024   // elements per scan block

// ---------------- scratch (no allocation allowed) ----------------
__device__ float g_h1[(size_t)NMAX * DH];     // x @ W1
__device__ float g_h2[(size_t)NMAX * DOUT];   // relu(agg1+b1) @ W2 (a1 never materialized)
__device__ int   g_deg[NMAX];
__device__ float g_dinv[NMAX];
__device__ int   g_rowptr[NMAX + 1];
__device__ int   g_cursor[NMAX];
__device__ int   g_csrsrc[EMAX];
__device__ int   g_blocksum[256];
__device__ int   g_blockoff[256];
__device__ int   g_is64;

__device__ __forceinline__ void get_edge(const void* ei, int e, int E, int& s, int& d) {
    if (g_is64) {
        const long long* p = (const long long*)ei;
        s = (int)p[e];
        d = (int)p[(size_t)E + e];
    } else {
        const int* p = (const int*)ei;
        s = p[e];
        d = p[E + e];
    }
}

// ---------------- init + fused edge-dtype detection ----------------
__global__ void init_kernel(const void* ei, int E, int n) {
    int v = blockIdx.x * blockDim.x + threadIdx.x;
    if (v < n) g_deg[v] = 0;
    if (blockIdx.x == 0 && threadIdx.x == 0) {
        // genuine int64 values are < 2^31; int32 misread as int64 has a random
        // node id in the high word -> >= 2^32 with overwhelming probability.
        const long long* p = (const long long*)ei;
        int m = E < 64 ? E : 64;
        int ok = 1;
        for (int i = 0; i < m; i++) {
            long long x = p[i];
            if (x < 0 || x >= (1LL << 31)) ok = 0;
        }
        g_is64 = ok;
    }
}

__global__ void count_kernel(const void* ei, int E) {
    int stride = gridDim.x * blockDim.x;
    for (int e = blockIdx.x * blockDim.x + threadIdx.x; e < E; e += stride) {
        int s, d;
        get_edge(ei, e, E, s, d);
        atomicAdd(&g_deg[d], 1);
    }
}

// ---- 3-phase scan ----
__global__ __launch_bounds__(1024) void scanA_kernel(int n) {
    __shared__ int sh[SCAN_B];
    int tid = threadIdx.x;
    int idx = blockIdx.x * SCAN_B + tid;
    int val = (idx < n) ? g_deg[idx] : 0;
    sh[tid] = val;
    __syncthreads();
    for (int off = 1; off < SCAN_B; off <<= 1) {
        int add = (tid >= off) ? sh[tid - off] : 0;
        __syncthreads();
        sh[tid] += add;
        __syncthreads();
    }
    if (idx < n) g_rowptr[idx] = sh[tid] - val;   // exclusive, block-local
    if (tid == SCAN_B - 1) g_blocksum[blockIdx.x] = sh[tid];
}

__global__ __launch_bounds__(256) void scanB_kernel(int nb, int n) {
    __shared__ int sh[256];
    int tid = threadIdx.x;
    int val = (tid < nb) ? g_blocksum[tid] : 0;
    sh[tid] = val;
    __syncthreads();
    for (int off = 1; off < 256; off <<= 1) {
        int add = (tid >= off) ? sh[tid - off] : 0;
        __syncthreads();
        sh[tid] += add;
        __syncthreads();
    }
    if (tid < nb) g_blockoff[tid] = sh[tid] - val;
    if (tid == 255) g_rowptr[n] = sh[255];        // total edge count
}

// Phase C: uniform add + fused prep (dinv, cursor).
__global__ void scanC_kernel(int n) {
    int v = blockIdx.x * blockDim.x + threadIdx.x;
    if (v < n) {
        int r = g_rowptr[v] + g_blockoff[v >> 10];
        g_rowptr[v] = r;
        g_cursor[v] = r;
        g_dinv[v] = rsqrtf((float)(g_deg[v] + 1));  // +1 self loop
    }
}

__global__ void fill_kernel(const void* ei, int E) {
    int stride = gridDim.x * blockDim.x;
    for (int e = blockIdx.x * blockDim.x + threadIdx.x; e < E; e += stride) {
        int s, d;
        get_edge(ei, e, E, s, d);
        int pos = atomicAdd(&g_cursor[d], 1);
        g_csrsrc[pos] = s;
    }
}

// ---------------- GEMM1: h1 = x @ W1  (N x 256 @ 256 x 128) ----------------
// 128x128 block tile, BK=8, 8x8 register tile, 256 threads,
// 2-stage software pipeline: next k-tile's LDGs overlap current compute.
__global__ __launch_bounds__(256) void gemm1_kernel(const float* __restrict__ x,
                                                    const float* __restrict__ W, int n) {
    __shared__ float As[8][128];
    __shared__ float Bs[8][128];
    int tid = threadIdx.x;
    int blockRow = blockIdx.x * 128;

    int aRow = tid >> 1;            // 0..127
    int aCol = (tid & 1) * 4;       // 0 or 4
    int bR = tid >> 5;              // 0..7
    int bC = (tid & 31) * 4;        // 0..124

    int tRow = (tid >> 4) * 8;      // 0..120
    int tCol = (tid & 15) * 8;      // 0..120

    float acc[8][8];
#pragma unroll
    for (int i = 0; i < 8; i++)
#pragma unroll
        for (int j = 0; j < 8; j++) acc[i][j] = 0.f;

    int gr = blockRow + aRow;
    bool rowOk = (gr < n);
    const float* aPtr = x + (size_t)(rowOk ? gr : 0) * DIN + aCol;
    const float* bPtr = W + (size_t)bR * DH + bC;

    // prologue: load k-tile 0
    float4 av = rowOk ? *(const float4*)(aPtr) : make_float4(0.f, 0.f, 0.f, 0.f);
    float4 bv = *(const float4*)(bPtr);

    for (int k0 = 0; k0 < DIN; k0 += 8) {
        // stage current tile into smem
        As[aCol + 0][aRow] = av.x;
        As[aCol + 1][aRow] = av.y;
        As[aCol + 2][aRow] = av.z;
        As[aCol + 3][aRow] = av.w;
        *(float4*)(&Bs[bR][bC]) = bv;
        __syncthreads();

        // prefetch next tile (overlaps with the FFMA loop below)
        if (k0 + 8 < DIN) {
            av = rowOk ? *(const float4*)(aPtr + k0 + 8) : make_float4(0.f, 0.f, 0.f, 0.f);
            bv = *(const float4*)(bPtr + (size_t)(k0 + 8) * DH);
        }

#pragma unroll
        for (int k = 0; k < 8; k++) {
            float rm[8], rn[8];
            *(float4*)(&rm[0]) = *(const float4*)(&As[k][tRow]);
            *(float4*)(&rm[4]) = *(const float4*)(&As[k][tRow + 4]);
            *(float4*)(&rn[0]) = *(const float4*)(&Bs[k][tCol]);
            *(float4*)(&rn[4]) = *(const float4*)(&Bs[k][tCol + 4]);
#pragma unroll
            for (int i = 0; i < 8; i++)
#pragma unroll
                for (int j = 0; j < 8; j++) acc[i][j] = fmaf(rm[i], rn[j], acc[i][j]);
        }
        __syncthreads();
    }

#pragma unroll
    for (int i = 0; i < 8; i++) {
        int r = blockRow + tRow + i;
        if (r < n) {
            float* o = g_h1 + (size_t)r * DH + tCol;
            *(float4*)(o + 0) = make_float4(acc[i][0], acc[i][1], acc[i][2], acc[i][3]);
            *(float4*)(o + 4) = make_float4(acc[i][4], acc[i][5], acc[i][6], acc[i][7]);
        }
    }
}

// ------- Aggregation 1 + bias + ReLU + GEMM2 fused (warp per node) -------
// a1 row lives only in registers; h2 = relu(agg(h1)+b1) @ W2 written directly.
__global__ __launch_bounds__(256) void agg1_gemm2_kernel(const float* __restrict__ b1,
                                                         const float* __restrict__ W2, int n) {
    __shared__ float Ws[DH * DOUT];   // 5 KB
    for (int i = threadIdx.x; i < DH * DOUT; i += 256) Ws[i] = W2[i];
    __syncthreads();

    int warp = (blockIdx.x * 256 + threadIdx.x) >> 5;
    int lane = threadIdx.x & 31;
    if (warp >= n) return;
    int v = warp;
    float dv = g_dinv[v];

    float4 acc = ((const float4*)(g_h1 + (size_t)v * DH))[lane];  // self loop
    float sw = dv * dv;
    acc.x *= sw; acc.y *= sw; acc.z *= sw; acc.w *= sw;

    int beg = g_rowptr[v], end = g_rowptr[v + 1];
    for (int base = beg; base < end; base += 32) {
        int j = base + lane;
        int s = 0;
        float w = 0.f;
        if (j < end) {
            s = g_csrsrc[j];
            w = g_dinv[s] * dv;
        }
        int cnt = min(32, end - base);
        for (int t = 0; t < cnt; t++) {
            int ss = __shfl_sync(0xffffffffu, s, t);
            float ww = __shfl_sync(0xffffffffu, w, t);
            float4 hv = ((const float4*)(g_h1 + (size_t)ss * DH))[lane];
            acc.x = fmaf(hv.x, ww, acc.x);
            acc.y = fmaf(hv.y, ww, acc.y);
            acc.z = fmaf(hv.z, ww, acc.z);
            acc.w = fmaf(hv.w, ww, acc.w);
        }
    }
    float4 b = ((const float4*)b1)[lane];
    float a[4];
    a[0] = fmaxf(acc.x + b.x, 0.f);
    a[1] = fmaxf(acc.y + b.y, 0.f);
    a[2] = fmaxf(acc.z + b.z, 0.f);
    a[3] = fmaxf(acc.w + b.w, 0.f);

    // fused GEMM2: p[d] = sum_k a1[k] * W2[k][d], k = lane*4 + c
    float p[DOUT];
#pragma unroll
    for (int d = 0; d < DOUT; d++) p[d] = 0.f;
    int k0 = lane * 4;
#pragma unroll
    for (int c = 0; c < 4; c++)
#pragma unroll
        for (int d = 0; d < DOUT; d++) p[d] = fmaf(a[c], Ws[(k0 + c) * DOUT + d], p[d]);
#pragma unroll
    for (int d = 0; d < DOUT; d++)
#pragma unroll
        for (int off = 16; off > 0; off >>= 1) p[d] += __shfl_down_sync(0xffffffffu, p[d], off);
    if (lane == 0) {
#pragma unroll
        for (int d = 0; d < DOUT; d++) g_h2[(size_t)v * DOUT + d] = p[d];
    }
}

// ---------------- Aggregation 2 + bias + log_softmax + output ----------------
__global__ void agg2_kernel(const float* __restrict__ b2, float* out_h, float* out_lsm, int n) {
    int v = blockIdx.x * blockDim.x + threadIdx.x;
    if (v >= n) return;
    float dv = g_dinv[v];
    float acc[DOUT];
    const float* hv = g_h2 + (size_t)v * DOUT;
    float sw = dv * dv;
#pragma unroll
    for (int d = 0; d < DOUT; d++) acc[d] = hv[d] * sw;

    int beg = g_rowptr[v], end = g_rowptr[v + 1];
    for (int j = beg; j < end; j++) {
        int s = g_csrsrc[j];
        float w = g_dinv[s] * dv;
        const float* hs = g_h2 + (size_t)s * DOUT;
#pragma unroll
        for (int d = 0; d < DOUT; d++) acc[d] = fmaf(hs[d], w, acc[d]);
    }
#pragma unroll
    for (int d = 0; d < DOUT; d++) acc[d] += b2[d];

    float m = acc[0];
#pragma unroll
    for (int d = 1; d < DOUT; d++) m = fmaxf(m, acc[d]);
    float se = 0.f;
#pragma unroll
    for (int d = 0; d < DOUT; d++) se += expf(acc[d] - m);
    float lse = m + logf(se);

    float* oh = out_h + (size_t)v * DOUT;
    float* ol = out_lsm + (size_t)v * DOUT;
#pragma unroll
    for (int d = 0; d < DOUT; d++) oh[d] = acc[d];
#pragma unroll
    for (int d = 0; d < DOUT; d++) ol[d] = acc[d] - lse;
}

// ---------------- launch ----------------
extern "C" void kernel_launch(void* const* d_in, const int* in_sizes, int n_in,
                              void* d_out, int out_size) {
    const float* x  = (const float*)d_in[0];
    const void*  ei = d_in[1];
    const float* W1 = (const float*)d_in[2];
    const float* b1 = (const float*)d_in[3];
    const float* W2 = (const float*)d_in[4];
    const float* b2 = (const float*)d_in[5];

    int n = in_sizes[0] / DIN;
    int E = in_sizes[1] / 2;
    if (n > NMAX) n = NMAX;
    if (E > EMAX) E = EMAX;

    float* out = (float*)d_out;
    float* out_h;
    float* out_lsm;
    if (out_size >= 2 * n * DOUT) {
        out_h = out;
        out_lsm = out + (size_t)n * DOUT;
    } else {
        out_h = out;       // overlapping: log_softmax (written last) wins
        out_lsm = out;
    }

    int nb256 = (n + 255) / 256;
    int nbScan = (n + SCAN_B - 1) / SCAN_B;
    int eb = 2048;

    init_kernel<<<nb256, 256>>>(ei, E, n);
    count_kernel<<<eb, 256>>>(ei, E);
    scanA_kernel<<<nbScan, 1024>>>(n);
    scanB_kernel<<<1, 256>>>(nbScan, n);
    scanC_kernel<<<nb256, 256>>>(n);
    fill_kernel<<<eb, 256>>>(ei, E);

    gemm1_kernel<<<(n + 127) / 128, 256>>>(x, W1, n);
    agg1_gemm2_kernel<<<(n * 32 + 255) / 256, 256>>>(b1, W2, n);
    agg2_kernel<<<nb256, 256>>>(b2, out_h, out_lsm, n);
}

// round 5
// speedup vs baseline: 1.5752x; 1.2337x over previous
#include <cuda_runtime.h>
#include <math.h>
#include <stdint.h>

#define NMAX 100000
#define EMAX 1600000
#define DIN 256
#define DH 128
#define DOUT 10
#define SCAN_B 1024   // elements per scan block

// ---------------- scratch (no allocation allowed) ----------------
__device__ float g_h1[(size_t)NMAX * DH];     // x @ W1
__device__ float g_h2[(size_t)NMAX * DOUT];   // relu(agg1+b1) @ W2 (a1 never materialized)
__device__ int   g_deg[NMAX];
__device__ float g_dinv[NMAX];
__device__ int   g_rowptr[NMAX + 1];
__device__ int   g_cursor[NMAX];
__device__ int   g_csrsrc[EMAX];
__device__ int   g_blocksum[256];
__device__ int   g_blockoff[256];
__device__ int   g_is64;

__device__ __forceinline__ void get_edge(const void* ei, int e, int E, int& s, int& d) {
    if (g_is64) {
        const long long* p = (const long long*)ei;
        s = (int)p[e];
        d = (int)p[(size_t)E + e];
    } else {
        const int* p = (const int*)ei;
        s = p[e];
        d = p[E + e];
    }
}

// ---------------- init + fused edge-dtype detection ----------------
__global__ void init_kernel(const void* ei, int E, int n) {
    int v = blockIdx.x * blockDim.x + threadIdx.x;
    if (v < n) g_deg[v] = 0;
    if (blockIdx.x == 0 && threadIdx.x == 0) {
        const long long* p = (const long long*)ei;
        int m = E < 64 ? E : 64;
        int ok = 1;
        for (int i = 0; i < m; i++) {
            long long x = p[i];
            if (x < 0 || x >= (1LL << 31)) ok = 0;
        }
        g_is64 = ok;
    }
}

__global__ void count_kernel(const void* ei, int E) {
    int stride = gridDim.x * blockDim.x;
    for (int e = blockIdx.x * blockDim.x + threadIdx.x; e < E; e += stride) {
        int s, d;
        get_edge(ei, e, E, s, d);
        atomicAdd(&g_deg[d], 1);
    }
}

// ---- 3-phase scan ----
__global__ __launch_bounds__(1024) void scanA_kernel(int n) {
    __shared__ int sh[SCAN_B];
    int tid = threadIdx.x;
    int idx = blockIdx.x * SCAN_B + tid;
    int val = (idx < n) ? g_deg[idx] : 0;
    sh[tid] = val;
    __syncthreads();
    for (int off = 1; off < SCAN_B; off <<= 1) {
        int add = (tid >= off) ? sh[tid - off] : 0;
        __syncthreads();
        sh[tid] += add;
        __syncthreads();
    }
    if (idx < n) g_rowptr[idx] = sh[tid] - val;   // exclusive, block-local
    if (tid == SCAN_B - 1) g_blocksum[blockIdx.x] = sh[tid];
}

__global__ __launch_bounds__(256) void scanB_kernel(int nb, int n) {
    __shared__ int sh[256];
    int tid = threadIdx.x;
    int val = (tid < nb) ? g_blocksum[tid] : 0;
    sh[tid] = val;
    __syncthreads();
    for (int off = 1; off < 256; off <<= 1) {
        int add = (tid >= off) ? sh[tid - off] : 0;
        __syncthreads();
        sh[tid] += add;
        __syncthreads();
    }
    if (tid < nb) g_blockoff[tid] = sh[tid] - val;
    if (tid == 255) g_rowptr[n] = sh[255];        // total edge count
}

// Phase C: uniform add + fused prep (dinv, cursor).
__global__ void scanC_kernel(int n) {
    int v = blockIdx.x * blockDim.x + threadIdx.x;
    if (v < n) {
        int r = g_rowptr[v] + g_blockoff[v >> 10];
        g_rowptr[v] = r;
        g_cursor[v] = r;
        g_dinv[v] = rsqrtf((float)(g_deg[v] + 1));  // +1 self loop
    }
}

__global__ void fill_kernel(const void* ei, int E) {
    int stride = gridDim.x * blockDim.x;
    for (int e = blockIdx.x * blockDim.x + threadIdx.x; e < E; e += stride) {
        int s, d;
        get_edge(ei, e, E, s, d);
        int pos = atomicAdd(&g_cursor[d], 1);
        g_csrsrc[pos] = s;
    }
}

// ============ GEMM1 via tensor cores: h1 = x @ W1 (3xTF32 split) ============
// CTA: 128(M) x 128(N), BK=16, 8 warps in 4(M) x 2(N) grid, warp tile 32x64.
// mma.sync.m16n8k8 row.col f32.tf32.tf32.f32, a = a_hi + a_lo exact split.
// cp.async double-buffered smem; pads chosen for 0 bank conflicts.

#define G1_BK 16
#define A_STRIDE 20    // (20*r + c) % 32 == (4r+c)%32: distinct across frag lanes
#define B_STRIDE 136   // (136*k + n) % 32 == (8k+n)%32: distinct across frag lanes

__device__ __forceinline__ void cp16(float* dst_smem, const float* src, bool valid) {
    uint32_t d = (uint32_t)__cvta_generic_to_shared(dst_smem);
    int sz = valid ? 16 : 0;
    asm volatile("cp.async.cg.shared.global [%0], [%1], 16, %2;"
                 :: "r"(d), "l"(src), "r"(sz));
}
__device__ __forceinline__ void cp_commit() { asm volatile("cp.async.commit_group;"); }
template <int N> __device__ __forceinline__ void cp_wait() {
    asm volatile("cp.async.wait_group %0;" :: "n"(N));
}

// exact fp32 -> tf32_hi + tf32_lo split (truncation; residual exact in fp32)
__device__ __forceinline__ void tf32_split(float v, uint32_t& hi, uint32_t& lo) {
    uint32_t u = __float_as_uint(v) & 0xFFFFE000u;
    float h = __uint_as_float(u);
    float l = v - h;
    hi = u;
    lo = __float_as_uint(l) & 0xFFFFE000u;
}

__device__ __forceinline__ void mma_tf32(float* d, const uint32_t* a, uint32_t b0, uint32_t b1) {
    asm volatile(
        "mma.sync.aligned.m16n8k8.row.col.f32.tf32.tf32.f32 "
        "{%0,%1,%2,%3}, {%4,%5,%6,%7}, {%8,%9}, {%0,%1,%2,%3};"
        : "+f"(d[0]), "+f"(d[1]), "+f"(d[2]), "+f"(d[3])
        : "r"(a[0]), "r"(a[1]), "r"(a[2]), "r"(a[3]), "r"(b0), "r"(b1));
}

__global__ __launch_bounds__(256) void gemm1_tc_kernel(const float* __restrict__ x,
                                                       const float* __restrict__ W, int n) {
    __shared__ float As[2][128][A_STRIDE];  // [stage][row][k]
    __shared__ float Bs[2][G1_BK][B_STRIDE];// [stage][k][n]

    int tid = threadIdx.x;
    int lane = tid & 31;
    int warp = tid >> 5;
    int wm = warp & 3;          // 0..3  -> M offset wm*32
    int wn = warp >> 2;         // 0..1  -> N offset wn*64
    int g = lane >> 2;          // groupID
    int tg = lane & 3;          // thread in group

    int blockRow = blockIdx.x * 128;

    float acc[2][8][4];
#pragma unroll
    for (int mf = 0; mf < 2; mf++)
#pragma unroll
        for (int nf = 0; nf < 8; nf++)
#pragma unroll
            for (int q = 0; q < 4; q++) acc[mf][nf][q] = 0.f;

    // per-thread cp.async assignments (2 A f4 + 2 B f4 per stage)
    int aIdx0 = tid * 2, aIdx1 = tid * 2 + 1;
    int aRow0 = aIdx0 >> 2, aC0 = (aIdx0 & 3) * 4;
    int aRow1 = aIdx1 >> 2, aC1 = (aIdx1 & 3) * 4;
    bool aOk0 = (blockRow + aRow0) < n;
    bool aOk1 = (blockRow + aRow1) < n;
    const float* aSrc0 = x + (size_t)(aOk0 ? blockRow + aRow0 : 0) * DIN + aC0;
    const float* aSrc1 = x + (size_t)(aOk1 ? blockRow + aRow1 : 0) * DIN + aC1;
    int bRow0 = aIdx0 >> 5, bC0 = (aIdx0 & 31) * 4;
    int bRow1 = aIdx1 >> 5, bC1 = (aIdx1 & 31) * 4;
    const float* bSrc0 = W + (size_t)bRow0 * DH + bC0;
    const float* bSrc1 = W + (size_t)bRow1 * DH + bC1;

    // prologue: stage 0 <- chunk 0
    cp16(&As[0][aRow0][aC0], aSrc0, aOk0);
    cp16(&As[0][aRow1][aC1], aSrc1, aOk1);
    cp16(&Bs[0][bRow0][bC0], bSrc0, true);
    cp16(&Bs[0][bRow1][bC1], bSrc1, true);
    cp_commit();

    const int NCHUNK = DIN / G1_BK;   // 16
    for (int kc = 0; kc < NCHUNK; kc++) {
        int s = kc & 1;
        if (kc + 1 < NCHUNK) {
            int ns = (kc + 1) & 1;
            int k0 = (kc + 1) * G1_BK;
            cp16(&As[ns][aRow0][aC0], aSrc0 + k0, aOk0);
            cp16(&As[ns][aRow1][aC1], aSrc1 + k0, aOk1);
            cp16(&Bs[ns][bRow0][bC0], bSrc0 + (size_t)k0 * DH, true);
            cp16(&Bs[ns][bRow1][bC1], bSrc1 + (size_t)k0 * DH, true);
            cp_commit();
            cp_wait<1>();
        } else {
            cp_wait<0>();
        }
        __syncthreads();

#pragma unroll
        for (int kk = 0; kk < G1_BK; kk += 8) {
            // A fragments (2 m-frags), split hi/lo
            uint32_t ahi[2][4], alo[2][4];
#pragma unroll
            for (int mf = 0; mf < 2; mf++) {
                int r = wm * 32 + mf * 16 + g;
                float a0 = As[s][r][kk + tg];
                float a1 = As[s][r + 8][kk + tg];
                float a2 = As[s][r][kk + tg + 4];
                float a3 = As[s][r + 8][kk + tg + 4];
                tf32_split(a0, ahi[mf][0], alo[mf][0]);
                tf32_split(a1, ahi[mf][1], alo[mf][1]);
                tf32_split(a2, ahi[mf][2], alo[mf][2]);
                tf32_split(a3, ahi[mf][3], alo[mf][3]);
            }
#pragma unroll
            for (int nf = 0; nf < 8; nf++) {
                int c = wn * 64 + nf * 8 + g;
                float b0 = Bs[s][kk + tg][c];
                float b1 = Bs[s][kk + tg + 4][c];
                uint32_t bh0, bl0, bh1, bl1;
                tf32_split(b0, bh0, bl0);
                tf32_split(b1, bh1, bl1);
#pragma unroll
                for (int mf = 0; mf < 2; mf++) {
                    mma_tf32(acc[mf][nf], ahi[mf], bh0, bh1);  // hi*hi
                    mma_tf32(acc[mf][nf], ahi[mf], bl0, bl1);  // hi*lo
                    mma_tf32(acc[mf][nf], alo[mf], bh0, bh1);  // lo*hi
                }
            }
        }
        __syncthreads();
    }

    // epilogue: scatter accumulators to g_h1
#pragma unroll
    for (int mf = 0; mf < 2; mf++) {
        int r0 = blockRow + wm * 32 + mf * 16 + g;
        int r1 = r0 + 8;
#pragma unroll
        for (int nf = 0; nf < 8; nf++) {
            int c = wn * 64 + nf * 8 + tg * 2;
            if (r0 < n)
                *(float2*)(g_h1 + (size_t)r0 * DH + c) = make_float2(acc[mf][nf][0], acc[mf][nf][1]);
            if (r1 < n)
                *(float2*)(g_h1 + (size_t)r1 * DH + c) = make_float2(acc[mf][nf][2], acc[mf][nf][3]);
        }
    }
}

// ------- Aggregation 1 + bias + ReLU + GEMM2 fused (warp per node) -------
__global__ __launch_bounds__(256) void agg1_gemm2_kernel(const float* __restrict__ b1,
                                                         const float* __restrict__ W2, int n) {
    __shared__ float Ws[DH * DOUT];   // 5 KB
    for (int i = threadIdx.x; i < DH * DOUT; i += 256) Ws[i] = W2[i];
    __syncthreads();

    int warp = (blockIdx.x * 256 + threadIdx.x) >> 5;
    int lane = threadIdx.x & 31;
    if (warp >= n) return;
    int v = warp;
    float dv = g_dinv[v];

    float4 acc = ((const float4*)(g_h1 + (size_t)v * DH))[lane];  // self loop
    float sw = dv * dv;
    acc.x *= sw; acc.y *= sw; acc.z *= sw; acc.w *= sw;

    int beg = g_rowptr[v], end = g_rowptr[v + 1];
    for (int base = beg; base < end; base += 32) {
        int j = base + lane;
        int s = 0;
        float w = 0.f;
        if (j < end) {
            s = g_csrsrc[j];
            w = g_dinv[s] * dv;
        }
        int cnt = min(32, end - base);
        for (int t = 0; t < cnt; t++) {
            int ss = __shfl_sync(0xffffffffu, s, t);
            float ww = __shfl_sync(0xffffffffu, w, t);
            float4 hv = ((const float4*)(g_h1 + (size_t)ss * DH))[lane];
            acc.x = fmaf(hv.x, ww, acc.x);
            acc.y = fmaf(hv.y, ww, acc.y);
            acc.z = fmaf(hv.z, ww, acc.z);
            acc.w = fmaf(hv.w, ww, acc.w);
        }
    }
    float4 b = ((const float4*)b1)[lane];
    float a[4];
    a[0] = fmaxf(acc.x + b.x, 0.f);
    a[1] = fmaxf(acc.y + b.y, 0.f);
    a[2] = fmaxf(acc.z + b.z, 0.f);
    a[3] = fmaxf(acc.w + b.w, 0.f);

    float p[DOUT];
#pragma unroll
    for (int d = 0; d < DOUT; d++) p[d] = 0.f;
    int k0 = lane * 4;
#pragma unroll
    for (int c = 0; c < 4; c++)
#pragma unroll
        for (int d = 0; d < DOUT; d++) p[d] = fmaf(a[c], Ws[(k0 + c) * DOUT + d], p[d]);
#pragma unroll
    for (int d = 0; d < DOUT; d++)
#pragma unroll
        for (int off = 16; off > 0; off >>= 1) p[d] += __shfl_down_sync(0xffffffffu, p[d], off);
    if (lane == 0) {
#pragma unroll
        for (int d = 0; d < DOUT; d++) g_h2[(size_t)v * DOUT + d] = p[d];
    }
}

// ---------------- Aggregation 2 + bias + log_softmax + output ----------------
__global__ void agg2_kernel(const float* __restrict__ b2, float* out_h, float* out_lsm, int n) {
    int v = blockIdx.x * blockDim.x + threadIdx.x;
    if (v >= n) return;
    float dv = g_dinv[v];
    float acc[DOUT];
    const float* hv = g_h2 + (size_t)v * DOUT;
    float sw = dv * dv;
#pragma unroll
    for (int d = 0; d < DOUT; d++) acc[d] = hv[d] * sw;

    int beg = g_rowptr[v], end = g_rowptr[v + 1];
    for (int j = beg; j < end; j++) {
        int s = g_csrsrc[j];
        float w = g_dinv[s] * dv;
        const float* hs = g_h2 + (size_t)s * DOUT;
#pragma unroll
        for (int d = 0; d < DOUT; d++) acc[d] = fmaf(hs[d], w, acc[d]);
    }
#pragma unroll
    for (int d = 0; d < DOUT; d++) acc[d] += b2[d];

    float m = acc[0];
#pragma unroll
    for (int d = 1; d < DOUT; d++) m = fmaxf(m, acc[d]);
    float se = 0.f;
#pragma unroll
    for (int d = 0; d < DOUT; d++) se += expf(acc[d] - m);
    float lse = m + logf(se);

    float* oh = out_h + (size_t)v * DOUT;
    float* ol = out_lsm + (size_t)v * DOUT;
#pragma unroll
    for (int d = 0; d < DOUT; d++) oh[d] = acc[d];
#pragma unroll
    for (int d = 0; d < DOUT; d++) ol[d] = acc[d] - lse;
}

// ---------------- launch ----------------
extern "C" void kernel_launch(void* const* d_in, const int* in_sizes, int n_in,
                              void* d_out, int out_size) {
    const float* x  = (const float*)d_in[0];
    const void*  ei = d_in[1];
    const float* W1 = (const float*)d_in[2];
    const float* b1 = (const float*)d_in[3];
    const float* W2 = (const float*)d_in[4];
    const float* b2 = (const float*)d_in[5];

    int n = in_sizes[0] / DIN;
    int E = in_sizes[1] / 2;
    if (n > NMAX) n = NMAX;
    if (E > EMAX) E = EMAX;

    float* out = (float*)d_out;
    float* out_h;
    float* out_lsm;
    if (out_size >= 2 * n * DOUT) {
        out_h = out;
        out_lsm = out + (size_t)n * DOUT;
    } else {
        out_h = out;       // overlapping: log_softmax (written last) wins
        out_lsm = out;
    }

    int nb256 = (n + 255) / 256;
    int nbScan = (n + SCAN_B - 1) / SCAN_B;
    int eb = 2048;

    init_kernel<<<nb256, 256>>>(ei, E, n);
    count_kernel<<<eb, 256>>>(ei, E);
    scanA_kernel<<<nbScan, 1024>>>(n);
    scanB_kernel<<<1, 256>>>(nbScan, n);
    scanC_kernel<<<nb256, 256>>>(n);
    fill_kernel<<<eb, 256>>>(ei, E);

    gemm1_tc_kernel<<<(n + 127) / 128, 256>>>(x, W1, n);
    agg1_gemm2_kernel<<<(n * 32 + 255) / 256, 256>>>(b1, W2, n);
    agg2_kernel<<<nb256, 256>>>(b2, out_h, out_lsm, n);
}

// round 7
// speedup vs baseline: 1.7204x; 1.0922x over previous
#include <cuda_runtime.h>
#include <math.h>
#include <stdint.h>

#define NMAX 100000
#define EMAX 1600000
#define DIN 256
#define DH 128
#define DOUT 10
#define SCAN_B 1024   // elements per scan block

// ---------------- scratch (no allocation allowed) ----------------
__device__ float g_h1[(size_t)NMAX * DH];     // x @ W1
__device__ float g_h2[(size_t)NMAX * DOUT];   // relu(agg1+b1) @ W2
__device__ int   g_deg[NMAX];
__device__ float g_dinv[NMAX];
__device__ int   g_rowptr[NMAX + 1];
__device__ int   g_cursor[NMAX];
__device__ int   g_csrsrc[EMAX];
__device__ int   g_blocksum[256];
__device__ int   g_blockoff[256];
__device__ int   g_is64;

// ---- streams/events for fork-join capture (created at program init; no device mem) ----
static cudaStream_t g_s2;
static cudaEvent_t g_evFork, g_evJoin;
static struct StreamInit {
    StreamInit() {
        cudaStreamCreateWithFlags(&g_s2, cudaStreamNonBlocking);
        cudaEventCreateWithFlags(&g_evFork, cudaEventDisableTiming);
        cudaEventCreateWithFlags(&g_evJoin, cudaEventDisableTiming);
    }
} g_streamInit;

__device__ __forceinline__ void get_edge(const void* ei, int e, int E, int& s, int& d) {
    if (g_is64) {
        const long long* p = (const long long*)ei;
        s = (int)p[e];
        d = (int)p[(size_t)E + e];
    } else {
        const int* p = (const int*)ei;
        s = p[e];
        d = p[E + e];
    }
}

// ---------------- init + fused edge-dtype detection ----------------
__global__ void init_kernel(const void* ei, int E, int n) {
    int v = blockIdx.x * blockDim.x + threadIdx.x;
    if (v < n) g_deg[v] = 0;
    if (blockIdx.x == 0 && threadIdx.x == 0) {
        const long long* p = (const long long*)ei;
        int m = E < 64 ? E : 64;
        int ok = 1;
        for (int i = 0; i < m; i++) {
            long long x = p[i];
            if (x < 0 || x >= (1LL << 31)) ok = 0;
        }
        g_is64 = ok;
    }
}

__global__ void count_kernel(const void* ei, int E) {
    int stride = gridDim.x * blockDim.x;
    for (int e = blockIdx.x * blockDim.x + threadIdx.x; e < E; e += stride) {
        int s, d;
        get_edge(ei, e, E, s, d);
        atomicAdd(&g_deg[d], 1);
    }
}

// ---- 3-phase scan ----
__global__ __launch_bounds__(1024) void scanA_kernel(int n) {
    __shared__ int sh[SCAN_B];
    int tid = threadIdx.x;
    int idx = blockIdx.x * SCAN_B + tid;
    int val = (idx < n) ? g_deg[idx] : 0;
    sh[tid] = val;
    __syncthreads();
    for (int off = 1; off < SCAN_B; off <<= 1) {
        int add = (tid >= off) ? sh[tid - off] : 0;
        __syncthreads();
        sh[tid] += add;
        __syncthreads();
    }
    if (idx < n) g_rowptr[idx] = sh[tid] - val;
    if (tid == SCAN_B - 1) g_blocksum[blockIdx.x] = sh[tid];
}

__global__ __launch_bounds__(256) void scanB_kernel(int nb, int n) {
    __shared__ int sh[256];
    int tid = threadIdx.x;
    int val = (tid < nb) ? g_blocksum[tid] : 0;
    sh[tid] = val;
    __syncthreads();
    for (int off = 1; off < 256; off <<= 1) {
        int add = (tid >= off) ? sh[tid - off] : 0;
        __syncthreads();
        sh[tid] += add;
        __syncthreads();
    }
    if (tid < nb) g_blockoff[tid] = sh[tid] - val;
    if (tid == 255) g_rowptr[n] = sh[255];
}

__global__ void scanC_kernel(int n) {
    int v = blockIdx.x * blockDim.x + threadIdx.x;
    if (v < n) {
        int r = g_rowptr[v] + g_blockoff[v >> 10];
        g_rowptr[v] = r;
        g_cursor[v] = r;
        g_dinv[v] = rsqrtf((float)(g_deg[v] + 1));  // +1 self loop
    }
}

__global__ void fill_kernel(const void* ei, int E) {
    int stride = gridDim.x * blockDim.x;
    for (int e = blockIdx.x * blockDim.x + threadIdx.x; e < E; e += stride) {
        int s, d;
        get_edge(ei, e, E, s, d);
        int pos = atomicAdd(&g_cursor[d], 1);
        g_csrsrc[pos] = s;
    }
}

// ============ GEMM1 via tensor cores: h1 = x @ W1 (3xTF32 split) ============
#define G1_BK 16
#define A_STRIDE 20
#define B_STRIDE 136

__device__ __forceinline__ void cp16(float* dst_smem, const float* src, bool valid) {
    uint32_t d = (uint32_t)__cvta_generic_to_shared(dst_smem);
    int sz = valid ? 16 : 0;
    asm volatile("cp.async.cg.shared.global [%0], [%1], 16, %2;"
                 :: "r"(d), "l"(src), "r"(sz));
}
__device__ __forceinline__ void cp_commit() { asm volatile("cp.async.commit_group;"); }
template <int N> __device__ __forceinline__ void cp_wait() {
    asm volatile("cp.async.wait_group %0;" :: "n"(N));
}

__device__ __forceinline__ void tf32_split(float v, uint32_t& hi, uint32_t& lo) {
    uint32_t u = __float_as_uint(v) & 0xFFFFE000u;
    float h = __uint_as_float(u);
    float l = v - h;
    hi = u;
    lo = __float_as_uint(l) & 0xFFFFE000u;
}

__device__ __forceinline__ void mma_tf32(float* d, const uint32_t* a, uint32_t b0, uint32_t b1) {
    asm volatile(
        "mma.sync.aligned.m16n8k8.row.col.f32.tf32.tf32.f32 "
        "{%0,%1,%2,%3}, {%4,%5,%6,%7}, {%8,%9}, {%0,%1,%2,%3};"
        : "+f"(d[0]), "+f"(d[1]), "+f"(d[2]), "+f"(d[3])
        : "r"(a[0]), "r"(a[1]), "r"(a[2]), "r"(a[3]), "r"(b0), "r"(b1));
}

__global__ __launch_bounds__(256) void gemm1_tc_kernel(const float* __restrict__ x,
                                                       const float* __restrict__ W, int n) {
    __shared__ float As[2][128][A_STRIDE];
    __shared__ float Bs[2][G1_BK][B_STRIDE];

    int tid = threadIdx.x;
    int lane = tid & 31;
    int warp = tid >> 5;
    int wm = warp & 3;
    int wn = warp >> 2;
    int g = lane >> 2;
    int tg = lane & 3;

    int blockRow = blockIdx.x * 128;

    float acc[2][8][4];
#pragma unroll
    for (int mf = 0; mf < 2; mf++)
#pragma unroll
        for (int nf = 0; nf < 8; nf++)
#pragma unroll
            for (int q = 0; q < 4; q++) acc[mf][nf][q] = 0.f;

    int aIdx0 = tid * 2, aIdx1 = tid * 2 + 1;
    int aRow0 = aIdx0 >> 2, aC0 = (aIdx0 & 3) * 4;
    int aRow1 = aIdx1 >> 2, aC1 = (aIdx1 & 3) * 4;
    bool aOk0 = (blockRow + aRow0) < n;
    bool aOk1 = (blockRow + aRow1) < n;
    const float* aSrc0 = x + (size_t)(aOk0 ? blockRow + aRow0 : 0) * DIN + aC0;
    const float* aSrc1 = x + (size_t)(aOk1 ? blockRow + aRow1 : 0) * DIN + aC1;
    int bRow0 = aIdx0 >> 5, bC0 = (aIdx0 & 31) * 4;
    int bRow1 = aIdx1 >> 5, bC1 = (aIdx1 & 31) * 4;
    const float* bSrc0 = W + (size_t)bRow0 * DH + bC0;
    const float* bSrc1 = W + (size_t)bRow1 * DH + bC1;

    cp16(&As[0][aRow0][aC0], aSrc0, aOk0);
    cp16(&As[0][aRow1][aC1], aSrc1, aOk1);
    cp16(&Bs[0][bRow0][bC0], bSrc0, true);
    cp16(&Bs[0][bRow1][bC1], bSrc1, true);
    cp_commit();

    const int NCHUNK = DIN / G1_BK;   // 16
    for (int kc = 0; kc < NCHUNK; kc++) {
        int s = kc & 1;
        if (kc + 1 < NCHUNK) {
            int ns = (kc + 1) & 1;
            int k0 = (kc + 1) * G1_BK;
            cp16(&As[ns][aRow0][aC0], aSrc0 + k0, aOk0);
            cp16(&As[ns][aRow1][aC1], aSrc1 + k0, aOk1);
            cp16(&Bs[ns][bRow0][bC0], bSrc0 + (size_t)k0 * DH, true);
            cp16(&Bs[ns][bRow1][bC1], bSrc1 + (size_t)k0 * DH, true);
            cp_commit();
            cp_wait<1>();
        } else {
            cp_wait<0>();
        }
        __syncthreads();

#pragma unroll
        for (int kk = 0; kk < G1_BK; kk += 8) {
            uint32_t ahi[2][4], alo[2][4];
#pragma unroll
            for (int mf = 0; mf < 2; mf++) {
                int r = wm * 32 + mf * 16 + g;
                float a0 = As[s][r][kk + tg];
                float a1 = As[s][r + 8][kk + tg];
                float a2 = As[s][r][kk + tg + 4];
                float a3 = As[s][r + 8][kk + tg + 4];
                tf32_split(a0, ahi[mf][0], alo[mf][0]);
                tf32_split(a1, ahi[mf][1], alo[mf][1]);
                tf32_split(a2, ahi[mf][2], alo[mf][2]);
                tf32_split(a3, ahi[mf][3], alo[mf][3]);
            }
#pragma unroll
            for (int nf = 0; nf < 8; nf++) {
                int c = wn * 64 + nf * 8 + g;
                float b0 = Bs[s][kk + tg][c];
                float b1 = Bs[s][kk + tg + 4][c];
                uint32_t bh0, bl0, bh1, bl1;
                tf32_split(b0, bh0, bl0);
                tf32_split(b1, bh1, bl1);
#pragma unroll
                for (int mf = 0; mf < 2; mf++) {
                    mma_tf32(acc[mf][nf], ahi[mf], bh0, bh1);
                    mma_tf32(acc[mf][nf], ahi[mf], bl0, bl1);
                    mma_tf32(acc[mf][nf], alo[mf], bh0, bh1);
                }
            }
        }
        __syncthreads();
    }

#pragma unroll
    for (int mf = 0; mf < 2; mf++) {
        int r0 = blockRow + wm * 32 + mf * 16 + g;
        int r1 = r0 + 8;
#pragma unroll
        for (int nf = 0; nf < 8; nf++) {
            int c = wn * 64 + nf * 8 + tg * 2;
            if (r0 < n)
                *(float2*)(g_h1 + (size_t)r0 * DH + c) = make_float2(acc[mf][nf][0], acc[mf][nf][1]);
            if (r1 < n)
                *(float2*)(g_h1 + (size_t)r1 * DH + c) = make_float2(acc[mf][nf][2], acc[mf][nf][3]);
        }
    }
}

// ------- Aggregation 1 + bias + ReLU + GEMM2 fused (warp per node) -------
// 4 neighbors per iteration: 4 independent LDG.128 in flight (MLP=4).
__global__ __launch_bounds__(256) void agg1_gemm2_kernel(const float* __restrict__ b1,
                                                         const float* __restrict__ W2, int n) {
    __shared__ float Ws[DH * DOUT];   // 5 KB
    for (int i = threadIdx.x; i < DH * DOUT; i += 256) Ws[i] = W2[i];
    __syncthreads();

    int warp = (blockIdx.x * 256 + threadIdx.x) >> 5;
    int lane = threadIdx.x & 31;
    if (warp >= n) return;
    int v = warp;
    float dv = g_dinv[v];

    float4 acc = ((const float4*)(g_h1 + (size_t)v * DH))[lane];  // self loop
    float sw = dv * dv;
    acc.x *= sw; acc.y *= sw; acc.z *= sw; acc.w *= sw;

    int beg = g_rowptr[v], end = g_rowptr[v + 1];
    for (int base = beg; base < end; base += 32) {
        int j = base + lane;
        int s = 0;
        float w = 0.f;
        if (j < end) {
            s = g_csrsrc[j];
            w = g_dinv[s] * dv;
        }
        int cnt = min(32, end - base);
        int t = 0;
        for (; t + 4 <= cnt; t += 4) {
            int s0 = __shfl_sync(0xffffffffu, s, t + 0);
            int s1 = __shfl_sync(0xffffffffu, s, t + 1);
            int s2 = __shfl_sync(0xffffffffu, s, t + 2);
            int s3 = __shfl_sync(0xffffffffu, s, t + 3);
            float w0 = __shfl_sync(0xffffffffu, w, t + 0);
            float w1 = __shfl_sync(0xffffffffu, w, t + 1);
            float w2 = __shfl_sync(0xffffffffu, w, t + 2);
            float w3 = __shfl_sync(0xffffffffu, w, t + 3);
            float4 v0 = ((const float4*)(g_h1 + (size_t)s0 * DH))[lane];
            float4 v1 = ((const float4*)(g_h1 + (size_t)s1 * DH))[lane];
            float4 v2 = ((const float4*)(g_h1 + (size_t)s2 * DH))[lane];
            float4 v3 = ((const float4*)(g_h1 + (size_t)s3 * DH))[lane];
            acc.x = fmaf(v0.x, w0, acc.x); acc.y = fmaf(v0.y, w0, acc.y);
            acc.z = fmaf(v0.z, w0, acc.z); acc.w = fmaf(v0.w, w0, acc.w);
            acc.x = fmaf(v1.x, w1, acc.x); acc.y = fmaf(v1.y, w1, acc.y);
            acc.z = fmaf(v1.z, w1, acc.z); acc.w = fmaf(v1.w, w1, acc.w);
            acc.x = fmaf(v2.x, w2, acc.x); acc.y = fmaf(v2.y, w2, acc.y);
            acc.z = fmaf(v2.z, w2, acc.z); acc.w = fmaf(v2.w, w2, acc.w);
            acc.x = fmaf(v3.x, w3, acc.x); acc.y = fmaf(v3.y, w3, acc.y);
            acc.z = fmaf(v3.z, w3, acc.z); acc.w = fmaf(v3.w, w3, acc.w);
        }
        for (; t < cnt; t++) {
            int ss = __shfl_sync(0xffffffffu, s, t);
            float ww = __shfl_sync(0xffffffffu, w, t);
            float4 hv = ((const float4*)(g_h1 + (size_t)ss * DH))[lane];
            acc.x = fmaf(hv.x, ww, acc.x);
            acc.y = fmaf(hv.y, ww, acc.y);
            acc.z = fmaf(hv.z, ww, acc.z);
            acc.w = fmaf(hv.w, ww, acc.w);
        }
    }
    float4 b = ((const float4*)b1)[lane];
    float a[4];
    a[0] = fmaxf(acc.x + b.x, 0.f);
    a[1] = fmaxf(acc.y + b.y, 0.f);
    a[2] = fmaxf(acc.z + b.z, 0.f);
    a[3] = fmaxf(acc.w + b.w, 0.f);

    float p[DOUT];
#pragma unroll
    for (int d = 0; d < DOUT; d++) p[d] = 0.f;
    int k0 = lane * 4;
#pragma unroll
    for (int c = 0; c < 4; c++)
#pragma unroll
        for (int d = 0; d < DOUT; d++) p[d] = fmaf(a[c], Ws[(k0 + c) * DOUT + d], p[d]);
#pragma unroll
    for (int d = 0; d < DOUT; d++)
#pragma unroll
        for (int off = 16; off > 0; off >>= 1) p[d] += __shfl_down_sync(0xffffffffu, p[d], off);
    if (lane == 0) {
#pragma unroll
        for (int d = 0; d < DOUT; d++) g_h2[(size_t)v * DOUT + d] = p[d];
    }
}

// ---------------- Aggregation 2 + bias + log_softmax + output ----------------
__global__ void agg2_kernel(const float* __restrict__ b2, float* out_h, float* out_lsm, int n) {
    int v = blockIdx.x * blockDim.x + threadIdx.x;
    if (v >= n) return;
    float dv = g_dinv[v];
    float acc[DOUT];
    const float* hv = g_h2 + (size_t)v * DOUT;
    float sw = dv * dv;
#pragma unroll
    for (int d = 0; d < DOUT; d++) acc[d] = hv[d] * sw;

    int beg = g_rowptr[v], end = g_rowptr[v + 1];
    for (int j = beg; j < end; j++) {
        int s = g_csrsrc[j];
        float w = g_dinv[s] * dv;
        const float* hs = g_h2 + (size_t)s * DOUT;
#pragma unroll
        for (int d = 0; d < DOUT; d++) acc[d] = fmaf(hs[d], w, acc[d]);
    }
#pragma unroll
    for (int d = 0; d < DOUT; d++) acc[d] += b2[d];

    float m = acc[0];
#pragma unroll
    for (int d = 1; d < DOUT; d++) m = fmaxf(m, acc[d]);
    float se = 0.f;
#pragma unroll
    for (int d = 0; d < DOUT; d++) se += expf(acc[d] - m);
    float lse = m + logf(se);

    float* oh = out_h + (size_t)v * DOUT;
    float* ol = out_lsm + (size_t)v * DOUT;
#pragma unroll
    for (int d = 0; d < DOUT; d++) oh[d] = acc[d];
#pragma unroll
    for (int d = 0; d < DOUT; d++) ol[d] = acc[d] - lse;
}

// ---------------- launch: fork CSR build || GEMM1, join before agg1 ----------------
extern "C" void kernel_launch(void* const* d_in, const int* in_sizes, int n_in,
                              void* d_out, int out_size) {
    const float* x  = (const float*)d_in[0];
    const void*  ei = d_in[1];
    const float* W1 = (const float*)d_in[2];
    const float* b1 = (const float*)d_in[3];
    const float* W2 = (const float*)d_in[4];
    const float* b2 = (const float*)d_in[5];

    int n = in_sizes[0] / DIN;
    int E = in_sizes[1] / 2;
    if (n > NMAX) n = NMAX;
    if (E > EMAX) E = EMAX;

    float* out = (float*)d_out;
    float* out_h;
    float* out_lsm;
    if (out_size >= 2 * n * DOUT) {
        out_h = out;
        out_lsm = out + (size_t)n * DOUT;
    } else {
        out_h = out;
        out_lsm = out;
    }

    int nb256 = (n + 255) / 256;
    int nbScan = (n + SCAN_B - 1) / SCAN_B;
    int eb = 2048;

    // fork: CSR build chain on g_s2, GEMM1 on main stream (independent work)
    cudaEventRecord(g_evFork, 0);
    cudaStreamWaitEvent(g_s2, g_evFork, 0);

    init_kernel<<<nb256, 256, 0, g_s2>>>(ei, E, n);
    count_kernel<<<eb, 256, 0, g_s2>>>(ei, E);
    scanA_kernel<<<nbScan, 1024, 0, g_s2>>>(n);
    scanB_kernel<<<1, 256, 0, g_s2>>>(nbScan, n);
    scanC_kernel<<<nb256, 256, 0, g_s2>>>(n);
    fill_kernel<<<eb, 256, 0, g_s2>>>(ei, E);
    cudaEventRecord(g_evJoin, g_s2);

    gemm1_tc_kernel<<<(n + 127) / 128, 256>>>(x, W1, n);

    // join: agg1 needs both CSR and h1
    cudaStreamWaitEvent(0, g_evJoin, 0);
    agg1_gemm2_kernel<<<(n * 32 + 255) / 256, 256>>>(b1, W2, n);
    agg2_kernel<<<nb256, 256>>>(b2, out_h, out_lsm, n);
}